// round 3
// baseline (speedup 1.0000x reference)
#include <cuda_runtime.h>
#include <cuda_fp16.h>

#define CC   256
#define NSP  110592   // 48^3 spatial
#define BATCH 2
#define EPS 1e-5f
#define GCHUNK 2048
#define NCHUNKS 54    // 54*2048 = 110592
#define KT 32

// ---------------- scratch (device globals; no allocation allowed) ----------------
__device__ float g_sum[BATCH][CC];
__device__ float g_sumsq[BATCH][CC];
__device__ float g_mean[BATCH][CC];
__device__ float g_rstd[BATCH][CC];
__device__ float g_G[BATCH][CC][CC];
__device__ float g_Wp[BATCH][3][CC][CC];   // folded W' = W * diag(rstd), p=0:q 1:k 2:v
__device__ float g_beta[BATCH][3][CC];     // beta_p = b_p - W'_p @ mean
__device__ float g_u[BATCH][CC];           // Wq' @ rowsum(x)
__device__ float g_sv[BATCH][CC];          // Wk' @ rowsum(x)
__device__ float g_T1[BATCH][CC][CC];      // G @ Wk'^T
__device__ float g_scores[BATCH][CC][CC];
__device__ float g_att[BATCH][CC][CC];
__device__ float g_M[BATCH][CC][CC];       // atten @ Wv'
__device__ float g_And[BATCH][CC][CC];     // A with zeroed diagonal
__device__ float g_adiag[BATCH][CC];       // M[o,o] + rstd[o]
__device__ float g_dvec[BATCH][CC];        // atten@betav - rstd*mean

// ---------------- helpers ----------------
__device__ __forceinline__ void mma16(float* c, const unsigned* a, const unsigned* b) {
    asm volatile(
        "mma.sync.aligned.m16n8k16.row.col.f32.f16.f16.f32 "
        "{%0,%1,%2,%3}, {%4,%5,%6,%7}, {%8,%9}, {%0,%1,%2,%3};\n"
        : "+f"(c[0]), "+f"(c[1]), "+f"(c[2]), "+f"(c[3])
        : "r"(a[0]), "r"(a[1]), "r"(a[2]), "r"(a[3]), "r"(b[0]), "r"(b[1]));
}
__device__ __forceinline__ unsigned packh2(__half a, __half b) {
    __half2 h = __halves2half2(a, b);
    return *(unsigned*)&h;
}

// ---------------- 1. per-(b,c) sum / sumsq over N, and zero G ----------------
__global__ void stats_kernel(const float* __restrict__ x) {
    int c = blockIdx.x, b = blockIdx.y, tid = threadIdx.x;
    const float4* row = (const float4*)(x + ((size_t)b * CC + c) * NSP);
    float s = 0.f, ss = 0.f;
    for (int i = tid; i < NSP / 4; i += 256) {
        float4 v = row[i];
        s  += v.x + v.y + v.z + v.w;
        ss += v.x * v.x + v.y * v.y + v.z * v.z + v.w * v.w;
    }
    __shared__ float sh1[256], sh2[256];
    sh1[tid] = s; sh2[tid] = ss; __syncthreads();
    for (int o = 128; o > 0; o >>= 1) {
        if (tid < o) { sh1[tid] += sh1[tid + o]; sh2[tid] += sh2[tid + o]; }
        __syncthreads();
    }
    if (tid == 0) { g_sum[b][c] = sh1[0]; g_sumsq[b][c] = sh2[0]; }
    g_G[b][c][tid] = 0.f;   // zero one row of G per block
}

// ---------------- 2. mean / rstd ----------------
__global__ void mr_kernel() {
    int t = threadIdx.x;            // 512 threads
    int b = t >> 8, c = t & 255;
    float m = g_sum[b][c] * (1.f / (float)NSP);
    float var = g_sumsq[b][c] * (1.f / (float)NSP) - m * m;
    g_mean[b][c] = m;
    g_rstd[b][c] = rsqrtf(var + EPS);
}

// ---------------- 3. Gram: G = x @ x^T (plain fp16 mma, atomic accumulate) ----------------
// fp16 rounding error random-walks over K=110592 -> |dG| ~ 0.2, |dscores| ~ 0.07,
// vs logit spread O(10^3): softmax-safe.
__global__ __launch_bounds__(256) void gram_kernel(const float* __restrict__ x) {
    int tile = blockIdx.x, b = blockIdx.z;
    int ti = tile >> 1, tj = tile & 1;
    size_t n0 = (size_t)blockIdx.y * GCHUNK;
    const float* xb = x + (size_t)b * CC * NSP;
    __shared__ __half As[128][KT + 8];
    __shared__ __half Bs[128][KT + 8];
    int tid = threadIdx.x, warp = tid >> 5, lane = tid & 31;
    int wm = warp & 1, wn = warp >> 1;   // 2 x 4 warp grid: 64x32 per warp
    float acc[4][4][4] = {};
    const float* Abase = xb + (size_t)(ti * 128) * NSP + n0;
    const float* Bbase = xb + (size_t)(tj * 128) * NSP + n0;
    for (int kt = 0; kt < GCHUNK; kt += KT) {
#pragma unroll
        for (int i = 0; i < 4; i++) {
            int idx = tid + i * 256;
            int r = idx >> 3, c4 = (idx & 7) << 2;
            float4 v = *(const float4*)(Abase + (size_t)r * NSP + kt + c4);
            *(__half2*)&As[r][c4]     = __floats2half2_rn(v.x, v.y);
            *(__half2*)&As[r][c4 + 2] = __floats2half2_rn(v.z, v.w);
            float4 w = *(const float4*)(Bbase + (size_t)r * NSP + kt + c4);
            *(__half2*)&Bs[r][c4]     = __floats2half2_rn(w.x, w.y);
            *(__half2*)&Bs[r][c4 + 2] = __floats2half2_rn(w.z, w.w);
        }
        __syncthreads();
#pragma unroll
        for (int ks = 0; ks < KT; ks += 16) {
            unsigned af[4][4], bf[4][2];
#pragma unroll
            for (int mi = 0; mi < 4; mi++) {
                int rb = wm * 64 + mi * 16 + (lane >> 2);
                int cb = ks + ((lane & 3) << 1);
                af[mi][0] = *(const unsigned*)&As[rb][cb];
                af[mi][1] = *(const unsigned*)&As[rb + 8][cb];
                af[mi][2] = *(const unsigned*)&As[rb][cb + 8];
                af[mi][3] = *(const unsigned*)&As[rb + 8][cb + 8];
            }
#pragma unroll
            for (int ni = 0; ni < 4; ni++) {
                int nb = wn * 32 + ni * 8 + (lane >> 2);
                int kb = ks + ((lane & 3) << 1);
                bf[ni][0] = *(const unsigned*)&Bs[nb][kb];
                bf[ni][1] = *(const unsigned*)&Bs[nb][kb + 8];
            }
#pragma unroll
            for (int mi = 0; mi < 4; mi++)
#pragma unroll
                for (int ni = 0; ni < 4; ni++)
                    mma16(acc[mi][ni], af[mi], bf[ni]);
        }
        __syncthreads();
    }
#pragma unroll
    for (int mi = 0; mi < 4; mi++)
#pragma unroll
        for (int ni = 0; ni < 4; ni++)
#pragma unroll
            for (int i = 0; i < 4; i++) {
                int row = ti * 128 + wm * 64 + mi * 16 + (lane >> 2) + 8 * (i >> 1);
                int col = tj * 128 + wn * 32 + ni * 8 + 2 * (lane & 3) + (i & 1);
                atomicAdd(&g_G[b][row][col], acc[mi][ni][i]);
            }
}

// ---------------- 4. fold weights + per-row dots ----------------
__global__ void fold_kernel(const float* __restrict__ Wq, const float* __restrict__ bq,
                            const float* __restrict__ Wk, const float* __restrict__ bk,
                            const float* __restrict__ Wv, const float* __restrict__ bv) {
    int o = blockIdx.x, p = blockIdx.y, b = blockIdx.z, c = threadIdx.x;
    const float* W    = (p == 0) ? Wq : (p == 1) ? Wk : Wv;
    const float* bias = (p == 0) ? bq : (p == 1) ? bk : bv;
    float wp = W[o * CC + c] * g_rstd[b][c];
    g_Wp[b][p][o][c] = wp;
    __shared__ float s1[256], s2[256];
    s1[c] = wp * g_mean[b][c];
    s2[c] = wp * g_sum[b][c];
    __syncthreads();
    for (int off = 128; off > 0; off >>= 1) {
        if (c < off) { s1[c] += s1[c + off]; s2[c] += s2[c + off]; }
        __syncthreads();
    }
    if (c == 0) {
        g_beta[b][p][o] = bias[o] - s1[0];
        if (p == 0) g_u[b][o]  = s2[0];
        if (p == 1) g_sv[b][o] = s2[0];
    }
}

// ---------------- 5. small 256x256x256 GEMMs (fp32, selector) ----------------
// which=0: T1 = G @ Wk'^T      (transB)
// which=1: scores = Wq' @ T1 + rank-1 terms
// which=2: M = atten @ Wv'
__global__ void sgemm_kernel(int which) {
    int b = blockIdx.z;
    const float *A, *B; float* Cm; int transB = 0, rank1 = 0;
    if (which == 0)      { A = &g_G[b][0][0];      B = &g_Wp[b][1][0][0]; Cm = &g_T1[b][0][0];     transB = 1; }
    else if (which == 1) { A = &g_Wp[b][0][0][0];  B = &g_T1[b][0][0];    Cm = &g_scores[b][0][0]; rank1 = 1;  }
    else                 { A = &g_att[b][0][0];    B = &g_Wp[b][2][0][0]; Cm = &g_M[b][0][0]; }
    int r0 = blockIdx.y * 32, c0 = blockIdx.x * 32;
    __shared__ float As[32][33], Bs[32][33];
    int tid = threadIdx.x;
    int tx = tid & 15, ty = tid >> 4;
    float acc[2][2] = {};
    for (int k0 = 0; k0 < CC; k0 += 32) {
#pragma unroll
        for (int t = 0; t < 4; t++) {
            int idx = tid + t * 256;
            int r = idx >> 5, cc = idx & 31;
            As[r][cc] = A[(r0 + r) * CC + k0 + cc];
            Bs[r][cc] = transB ? B[(c0 + cc) * CC + k0 + r] : B[(k0 + r) * CC + c0 + cc];
        }
        __syncthreads();
#pragma unroll
        for (int k = 0; k < 32; k++) {
            float a0 = As[ty * 2][k], a1 = As[ty * 2 + 1][k];
            float b0 = Bs[k][tx * 2], b1 = Bs[k][tx * 2 + 1];
            acc[0][0] += a0 * b0; acc[0][1] += a0 * b1;
            acc[1][0] += a1 * b0; acc[1][1] += a1 * b1;
        }
        __syncthreads();
    }
#pragma unroll
    for (int i = 0; i < 2; i++)
#pragma unroll
        for (int j = 0; j < 2; j++) {
            int r = r0 + ty * 2 + i, cc = c0 + tx * 2 + j;
            float v = acc[i][j];
            if (rank1)
                v += g_u[b][r] * g_beta[b][1][cc]
                   + g_beta[b][0][r] * g_sv[b][cc]
                   + (float)NSP * g_beta[b][0][r] * g_beta[b][1][cc];
            Cm[r * CC + cc] = v;
        }
}

// ---------------- 6. softmax rows -> atten ----------------
__global__ void softmax_kernel(const float* __restrict__ outer) {
    int o = blockIdx.x, b = blockIdx.y, d = threadIdx.x;
    float v = g_scores[b][o][d];
    __shared__ float sh[256];
    sh[d] = v; __syncthreads();
    for (int off = 128; off > 0; off >>= 1) {
        if (d < off) sh[d] = fmaxf(sh[d], sh[d + off]);
        __syncthreads();
    }
    float mx = sh[0]; __syncthreads();
    float e = expf(v - mx);
    sh[d] = e; __syncthreads();
    for (int off = 128; off > 0; off >>= 1) {
        if (d < off) sh[d] += sh[d + off];
        __syncthreads();
    }
    float inv = 1.f / sh[0];
    g_att[b][o][d] = e * inv * 0.0625f + outer[o * CC + d] * 0.0625f;
}

// ---------------- 7. finalize A_nd / adiag / dvec ----------------
__global__ void fin_kernel() {
    int o = blockIdx.x, b = blockIdx.y, c = threadIdx.x;
    float m = g_M[b][o][c];
    g_And[b][o][c] = (c == o) ? 0.f : m;
    __shared__ float sh[256];
    __shared__ float mdiag;
    if (c == o) mdiag = m;
    sh[c] = g_att[b][o][c] * g_beta[b][2][c];
    __syncthreads();
    for (int off = 128; off > 0; off >>= 1) {
        if (c < off) sh[c] += sh[c + off];
        __syncthreads();
    }
    if (c == 0) {
        g_adiag[b][o] = mdiag + g_rstd[b][o];
        g_dvec[b][o]  = sh[0] - g_rstd[b][o] * g_mean[b][o];
    }
}

// ---------------- 8. final GEMM: out = A_nd @ x (fp16 split, 3 products)
//                    + adiag*x (exact fp32) + dvec ----------------
__global__ __launch_bounds__(256) void out_kernel(const float* __restrict__ x,
                                                  float* __restrict__ out) {
    int mt = blockIdx.x, nt = blockIdx.y, b = blockIdx.z;
    int m0 = mt * 128, n0 = nt * 128;
    const float* xb = x + (size_t)b * CC * NSP;
    float* ob = out + (size_t)b * CC * NSP;
    const float* Ab = &g_And[b][0][0];
    __shared__ __half Ah[128][KT + 8];
    __shared__ __half Al[128][KT + 8];
    __shared__ float Bs[KT][132];
    int tid = threadIdx.x, warp = tid >> 5, lane = tid & 31;
    int wm = warp & 1, wn = warp >> 1;
    float acc[4][4][4] = {};
    int   rows[4][2];
    float adv[4][2];
#pragma unroll
    for (int mi = 0; mi < 4; mi++)
#pragma unroll
        for (int rs = 0; rs < 2; rs++) {
            int r = wm * 64 + mi * 16 + (lane >> 2) + 8 * rs;
            rows[mi][rs] = r;
            adv[mi][rs] = g_adiag[b][m0 + r];
        }
    for (int kt = 0; kt < CC; kt += KT) {
#pragma unroll
        for (int i = 0; i < 4; i++) {        // A tile 128x32, split hi/lo fp16
            int idx = tid + i * 256;
            int r = idx >> 3, c4 = (idx & 7) << 2;
            float4 v = *(const float4*)(Ab + (size_t)(m0 + r) * CC + kt + c4);
            __half h0 = __float2half_rn(v.x), h1 = __float2half_rn(v.y);
            __half h2 = __float2half_rn(v.z), h3 = __float2half_rn(v.w);
            *(__half2*)&Ah[r][c4]     = __halves2half2(h0, h1);
            *(__half2*)&Ah[r][c4 + 2] = __halves2half2(h2, h3);
            *(__half2*)&Al[r][c4]     = __floats2half2_rn(v.x - __half2float(h0),
                                                          v.y - __half2float(h1));
            *(__half2*)&Al[r][c4 + 2] = __floats2half2_rn(v.z - __half2float(h2),
                                                          v.w - __half2float(h3));
        }
#pragma unroll
        for (int i = 0; i < 4; i++) {        // x tile 32x128, fp32 (exact diag path)
            int idx = tid + i * 256;
            int kk = idx >> 5, c4 = (idx & 31) << 2;
            float4 v = *(const float4*)(xb + (size_t)(kt + kk) * NSP + n0 + c4);
            *(float4*)&Bs[kk][c4] = v;
        }
        __syncthreads();
#pragma unroll
        for (int ks = 0; ks < KT; ks += 16) {
            unsigned ah[4][4], bh[4][2], bl[4][2];
#pragma unroll
            for (int ni = 0; ni < 4; ni++) {
                int nb = wn * 32 + ni * 8 + (lane >> 2);
                int kb = ks + ((lane & 3) << 1);
                float f0 = Bs[kb][nb],     f1 = Bs[kb + 1][nb];
                float f2 = Bs[kb + 8][nb], f3 = Bs[kb + 9][nb];
                __half h0 = __float2half_rn(f0), h1 = __float2half_rn(f1);
                __half h2 = __float2half_rn(f2), h3 = __float2half_rn(f3);
                bh[ni][0] = packh2(h0, h1);
                bh[ni][1] = packh2(h2, h3);
                bl[ni][0] = packh2(__float2half_rn(f0 - __half2float(h0)),
                                   __float2half_rn(f1 - __half2float(h1)));
                bl[ni][1] = packh2(__float2half_rn(f2 - __half2float(h2)),
                                   __float2half_rn(f3 - __half2float(h3)));
            }
#pragma unroll
            for (int mi = 0; mi < 4; mi++) {
                int rb = wm * 64 + mi * 16 + (lane >> 2);
                int cb = ks + ((lane & 3) << 1);
                ah[mi][0] = *(const unsigned*)&Ah[rb][cb];
                ah[mi][1] = *(const unsigned*)&Ah[rb + 8][cb];
                ah[mi][2] = *(const unsigned*)&Ah[rb][cb + 8];
                ah[mi][3] = *(const unsigned*)&Ah[rb + 8][cb + 8];
            }
#pragma unroll
            for (int mi = 0; mi < 4; mi++)
#pragma unroll
                for (int ni = 0; ni < 4; ni++) {
                    mma16(acc[mi][ni], ah[mi], bh[ni]);   // hi * hi
                    mma16(acc[mi][ni], ah[mi], bl[ni]);   // hi * lo
                }
#pragma unroll
            for (int mi = 0; mi < 4; mi++) {              // reload as lo(A)
                int rb = wm * 64 + mi * 16 + (lane >> 2);
                int cb = ks + ((lane & 3) << 1);
                ah[mi][0] = *(const unsigned*)&Al[rb][cb];
                ah[mi][1] = *(const unsigned*)&Al[rb + 8][cb];
                ah[mi][2] = *(const unsigned*)&Al[rb][cb + 8];
                ah[mi][3] = *(const unsigned*)&Al[rb + 8][cb + 8];
            }
#pragma unroll
            for (int mi = 0; mi < 4; mi++)
#pragma unroll
                for (int ni = 0; ni < 4; ni++)
                    mma16(acc[mi][ni], ah[mi], bh[ni]);   // lo * hi
        }
        // exact-fp32 diagonal (residual) contribution from this K tile
#pragma unroll
        for (int mi = 0; mi < 4; mi++)
#pragma unroll
            for (int rs = 0; rs < 2; rs++) {
                int gch = m0 + rows[mi][rs];
                if (gch >= kt && gch < kt + KT) {
                    int ks2 = gch - kt;
                    float av = adv[mi][rs];
#pragma unroll
                    for (int ni = 0; ni < 4; ni++) {
                        int nb = wn * 32 + ni * 8 + 2 * (lane & 3);
                        acc[mi][ni][rs * 2 + 0] += av * Bs[ks2][nb];
                        acc[mi][ni][rs * 2 + 1] += av * Bs[ks2][nb + 1];
                    }
                }
            }
        __syncthreads();
    }
#pragma unroll
    for (int mi = 0; mi < 4; mi++)
#pragma unroll
        for (int rs = 0; rs < 2; rs++) {
            int r = m0 + rows[mi][rs];
            float dv = g_dvec[b][r];
            float* orow = ob + (size_t)r * NSP + n0;
#pragma unroll
            for (int ni = 0; ni < 4; ni++) {
                int nb = wn * 32 + ni * 8 + 2 * (lane & 3);
                float2 v;
                v.x = acc[mi][ni][rs * 2 + 0] + dv;
                v.y = acc[mi][ni][rs * 2 + 1] + dv;
                *(float2*)&orow[nb] = v;
            }
        }
}

// ---------------- host ----------------
extern "C" void kernel_launch(void* const* d_in, const int* in_sizes, int n_in,
                              void* d_out, int out_size) {
    (void)in_sizes; (void)n_in; (void)out_size;
    const float* x     = (const float*)d_in[0];
    const float* Wq    = (const float*)d_in[1];
    const float* bq    = (const float*)d_in[2];
    const float* Wk    = (const float*)d_in[3];
    const float* bk    = (const float*)d_in[4];
    const float* Wv    = (const float*)d_in[5];
    const float* bv    = (const float*)d_in[6];
    const float* outer = (const float*)d_in[7];
    float* out = (float*)d_out;

    stats_kernel<<<dim3(CC, BATCH), 256>>>(x);
    mr_kernel<<<1, 512>>>();
    gram_kernel<<<dim3(4, NCHUNKS, BATCH), 256>>>(x);
    fold_kernel<<<dim3(CC, 3, BATCH), 256>>>(Wq, bq, Wk, bk, Wv, bv);
    sgemm_kernel<<<dim3(8, 8, BATCH), 256>>>(0);   // T1 = G @ Wk'^T
    sgemm_kernel<<<dim3(8, 8, BATCH), 256>>>(1);   // scores = Wq' @ T1 + rank1
    softmax_kernel<<<dim3(CC, BATCH), 256>>>(outer);
    sgemm_kernel<<<dim3(8, 8, BATCH), 256>>>(2);   // M = atten @ Wv'
    fin_kernel<<<dim3(CC, BATCH), 256>>>();
    out_kernel<<<dim3(2, 864, BATCH), 256>>>(x, out);
}

// round 4
// speedup vs baseline: 1.0834x; 1.0834x over previous
#include <cuda_runtime.h>
#include <cuda_fp16.h>

#define CC   256
#define NSP  110592   // 48^3 spatial
#define BATCH 2
#define EPS 1e-5f
#define GCHUNK 2048
#define NCHUNKS 54    // 54*2048 = 110592
#define KT 32

// ---------------- scratch (device globals; no allocation allowed) ----------------
__device__ float g_sum[BATCH][CC];
__device__ float g_sumsq[BATCH][CC];
__device__ float g_mean[BATCH][CC];
__device__ float g_rstd[BATCH][CC];
__device__ float g_G[BATCH][CC][CC];
__device__ float g_Wp[BATCH][3][CC][CC];   // folded W' = W * diag(rstd), p=0:q 1:k 2:v
__device__ float g_beta[BATCH][3][CC];     // beta_p = b_p - W'_p @ mean
__device__ float g_u[BATCH][CC];           // Wq' @ rowsum(x)
__device__ float g_sv[BATCH][CC];          // Wk' @ rowsum(x)
__device__ float g_T1[BATCH][CC][CC];      // G @ Wk'^T
__device__ float g_scores[BATCH][CC][CC];
__device__ float g_att[BATCH][CC][CC];
__device__ float g_M[BATCH][CC][CC];       // atten @ Wv'
__device__ float g_And[BATCH][CC][CC];     // A with zeroed diagonal
__device__ float g_adiag[BATCH][CC];       // M[o,o] + rstd[o]
__device__ float g_dvec[BATCH][CC];        // atten@betav - rstd*mean

// ---------------- helpers ----------------
__device__ __forceinline__ void mma16(float* c, const unsigned* a, const unsigned* b) {
    asm volatile(
        "mma.sync.aligned.m16n8k16.row.col.f32.f16.f16.f32 "
        "{%0,%1,%2,%3}, {%4,%5,%6,%7}, {%8,%9}, {%0,%1,%2,%3};\n"
        : "+f"(c[0]), "+f"(c[1]), "+f"(c[2]), "+f"(c[3])
        : "r"(a[0]), "r"(a[1]), "r"(a[2]), "r"(a[3]), "r"(b[0]), "r"(b[1]));
}

// ---------------- 1. per-(b,c) sum / sumsq over N, and zero G ----------------
__global__ void stats_kernel(const float* __restrict__ x) {
    int c = blockIdx.x, b = blockIdx.y, tid = threadIdx.x;
    const float4* row = (const float4*)(x + ((size_t)b * CC + c) * NSP);
    float s = 0.f, ss = 0.f;
    for (int i = tid; i < NSP / 4; i += 256) {
        float4 v = row[i];
        s  += v.x + v.y + v.z + v.w;
        ss += v.x * v.x + v.y * v.y + v.z * v.z + v.w * v.w;
    }
    __shared__ float sh1[256], sh2[256];
    sh1[tid] = s; sh2[tid] = ss; __syncthreads();
    for (int o = 128; o > 0; o >>= 1) {
        if (tid < o) { sh1[tid] += sh1[tid + o]; sh2[tid] += sh2[tid + o]; }
        __syncthreads();
    }
    if (tid == 0) { g_sum[b][c] = sh1[0]; g_sumsq[b][c] = sh2[0]; }
    g_G[b][c][tid] = 0.f;   // zero one row of G per block
}

// ---------------- 2. mean / rstd ----------------
__global__ void mr_kernel() {
    int t = threadIdx.x;            // 512 threads
    int b = t >> 8, c = t & 255;
    float m = g_sum[b][c] * (1.f / (float)NSP);
    float var = g_sumsq[b][c] * (1.f / (float)NSP) - m * m;
    g_mean[b][c] = m;
    g_rstd[b][c] = rsqrtf(var + EPS);
}

// ---------------- 3. Gram: G = x @ x^T (fp16 mma, symmetric: 3 of 4 tiles) ----------------
// tile 0 -> (0,0) diag; tile 1 -> (1,1) diag; tile 2 -> (0,1). (1,0) mirrored later.
__global__ __launch_bounds__(256) void gram_kernel(const float* __restrict__ x) {
    int tile = blockIdx.x, b = blockIdx.z;
    int diag = (tile < 2);
    int ti = (tile == 1) ? 1 : 0;
    int tj = (tile == 0) ? 0 : 1;
    size_t n0 = (size_t)blockIdx.y * GCHUNK;
    const float* xb = x + (size_t)b * CC * NSP;
    __shared__ __half As[128][KT + 8];
    __shared__ __half Bs[128][KT + 8];
    int tid = threadIdx.x, warp = tid >> 5, lane = tid & 31;
    int wm = warp & 1, wn = warp >> 1;   // 2 x 4 warp grid: 64x32 per warp
    float acc[4][4][4] = {};
    const float* Abase = xb + (size_t)(ti * 128) * NSP + n0;
    const float* Bbase = xb + (size_t)(tj * 128) * NSP + n0;
    for (int kt = 0; kt < GCHUNK; kt += KT) {
#pragma unroll
        for (int i = 0; i < 4; i++) {
            int idx = tid + i * 256;
            int r = idx >> 3, c4 = (idx & 7) << 2;
            float4 v = *(const float4*)(Abase + (size_t)r * NSP + kt + c4);
            *(__half2*)&As[r][c4]     = __floats2half2_rn(v.x, v.y);
            *(__half2*)&As[r][c4 + 2] = __floats2half2_rn(v.z, v.w);
            if (!diag) {
                float4 w = *(const float4*)(Bbase + (size_t)r * NSP + kt + c4);
                *(__half2*)&Bs[r][c4]     = __floats2half2_rn(w.x, w.y);
                *(__half2*)&Bs[r][c4 + 2] = __floats2half2_rn(w.z, w.w);
            }
        }
        __syncthreads();
        __half (*Bp)[KT + 8] = diag ? As : Bs;
#pragma unroll
        for (int ks = 0; ks < KT; ks += 16) {
            unsigned af[4][4], bf[4][2];
#pragma unroll
            for (int mi = 0; mi < 4; mi++) {
                int rb = wm * 64 + mi * 16 + (lane >> 2);
                int cb = ks + ((lane & 3) << 1);
                af[mi][0] = *(const unsigned*)&As[rb][cb];
                af[mi][1] = *(const unsigned*)&As[rb + 8][cb];
                af[mi][2] = *(const unsigned*)&As[rb][cb + 8];
                af[mi][3] = *(const unsigned*)&As[rb + 8][cb + 8];
            }
#pragma unroll
            for (int ni = 0; ni < 4; ni++) {
                int nb = wn * 32 + ni * 8 + (lane >> 2);
                int kb = ks + ((lane & 3) << 1);
                bf[ni][0] = *(const unsigned*)&Bp[nb][kb];
                bf[ni][1] = *(const unsigned*)&Bp[nb][kb + 8];
            }
#pragma unroll
            for (int mi = 0; mi < 4; mi++)
#pragma unroll
                for (int ni = 0; ni < 4; ni++)
                    mma16(acc[mi][ni], af[mi], bf[ni]);
        }
        __syncthreads();
    }
#pragma unroll
    for (int mi = 0; mi < 4; mi++)
#pragma unroll
        for (int ni = 0; ni < 4; ni++)
#pragma unroll
            for (int i = 0; i < 4; i++) {
                int row = ti * 128 + wm * 64 + mi * 16 + (lane >> 2) + 8 * (i >> 1);
                int col = tj * 128 + wn * 32 + ni * 8 + 2 * (lane & 3) + (i & 1);
                atomicAdd(&g_G[b][row][col], acc[mi][ni][i]);
            }
}

// ---------------- 3b. mirror lower-left block: G[128+i][j] = G[j][128+i] ----------------
__global__ void mirror_kernel() {
    int b = blockIdx.z;
    int r0 = blockIdx.y * 32;          // source rows 0..127
    int c0 = 128 + blockIdx.x * 32;    // source cols 128..255
    __shared__ float sh[32][33];
    int tx = threadIdx.x & 31, ty = threadIdx.x >> 5;   // 32 x 8
#pragma unroll
    for (int i = 0; i < 4; i++)
        sh[ty + i * 8][tx] = g_G[b][r0 + ty + i * 8][c0 + tx];
    __syncthreads();
#pragma unroll
    for (int i = 0; i < 4; i++)
        g_G[b][c0 + ty + i * 8][r0 + tx] = sh[tx][ty + i * 8];
}

// ---------------- 4. fold weights + per-row dots ----------------
__global__ void fold_kernel(const float* __restrict__ Wq, const float* __restrict__ bq,
                            const float* __restrict__ Wk, const float* __restrict__ bk,
                            const float* __restrict__ Wv, const float* __restrict__ bv) {
    int o = blockIdx.x, p = blockIdx.y, b = blockIdx.z, c = threadIdx.x;
    const float* W    = (p == 0) ? Wq : (p == 1) ? Wk : Wv;
    const float* bias = (p == 0) ? bq : (p == 1) ? bk : bv;
    float wp = W[o * CC + c] * g_rstd[b][c];
    g_Wp[b][p][o][c] = wp;
    __shared__ float s1[256], s2[256];
    s1[c] = wp * g_mean[b][c];
    s2[c] = wp * g_sum[b][c];
    __syncthreads();
    for (int off = 128; off > 0; off >>= 1) {
        if (c < off) { s1[c] += s1[c + off]; s2[c] += s2[c + off]; }
        __syncthreads();
    }
    if (c == 0) {
        g_beta[b][p][o] = bias[o] - s1[0];
        if (p == 0) g_u[b][o]  = s2[0];
        if (p == 1) g_sv[b][o] = s2[0];
    }
}

// ---------------- 5. small 256x256x256 GEMMs (fp32, selector) ----------------
__global__ void sgemm_kernel(int which) {
    int b = blockIdx.z;
    const float *A, *B; float* Cm; int transB = 0, rank1 = 0;
    if (which == 0)      { A = &g_G[b][0][0];      B = &g_Wp[b][1][0][0]; Cm = &g_T1[b][0][0];     transB = 1; }
    else if (which == 1) { A = &g_Wp[b][0][0][0];  B = &g_T1[b][0][0];    Cm = &g_scores[b][0][0]; rank1 = 1;  }
    else                 { A = &g_att[b][0][0];    B = &g_Wp[b][2][0][0]; Cm = &g_M[b][0][0]; }
    int r0 = blockIdx.y * 32, c0 = blockIdx.x * 32;
    __shared__ float As[32][33], Bs[32][33];
    int tid = threadIdx.x;
    int tx = tid & 15, ty = tid >> 4;
    float acc[2][2] = {};
    for (int k0 = 0; k0 < CC; k0 += 32) {
#pragma unroll
        for (int t = 0; t < 4; t++) {
            int idx = tid + t * 256;
            int r = idx >> 5, cc = idx & 31;
            As[r][cc] = A[(r0 + r) * CC + k0 + cc];
            Bs[r][cc] = transB ? B[(c0 + cc) * CC + k0 + r] : B[(k0 + r) * CC + c0 + cc];
        }
        __syncthreads();
#pragma unroll
        for (int k = 0; k < 32; k++) {
            float a0 = As[ty * 2][k], a1 = As[ty * 2 + 1][k];
            float b0 = Bs[k][tx * 2], b1 = Bs[k][tx * 2 + 1];
            acc[0][0] += a0 * b0; acc[0][1] += a0 * b1;
            acc[1][0] += a1 * b0; acc[1][1] += a1 * b1;
        }
        __syncthreads();
    }
#pragma unroll
    for (int i = 0; i < 2; i++)
#pragma unroll
        for (int j = 0; j < 2; j++) {
            int r = r0 + ty * 2 + i, cc = c0 + tx * 2 + j;
            float v = acc[i][j];
            if (rank1)
                v += g_u[b][r] * g_beta[b][1][cc]
                   + g_beta[b][0][r] * g_sv[b][cc]
                   + (float)NSP * g_beta[b][0][r] * g_beta[b][1][cc];
            Cm[r * CC + cc] = v;
        }
}

// ---------------- 6. softmax rows -> atten ----------------
__global__ void softmax_kernel(const float* __restrict__ outer) {
    int o = blockIdx.x, b = blockIdx.y, d = threadIdx.x;
    float v = g_scores[b][o][d];
    __shared__ float sh[256];
    sh[d] = v; __syncthreads();
    for (int off = 128; off > 0; off >>= 1) {
        if (d < off) sh[d] = fmaxf(sh[d], sh[d + off]);
        __syncthreads();
    }
    float mx = sh[0]; __syncthreads();
    float e = expf(v - mx);
    sh[d] = e; __syncthreads();
    for (int off = 128; off > 0; off >>= 1) {
        if (d < off) sh[d] += sh[d + off];
        __syncthreads();
    }
    float inv = 1.f / sh[0];
    g_att[b][o][d] = e * inv * 0.0625f + outer[o * CC + d] * 0.0625f;
}

// ---------------- 7. finalize A_nd / adiag / dvec ----------------
__global__ void fin_kernel() {
    int o = blockIdx.x, b = blockIdx.y, c = threadIdx.x;
    float m = g_M[b][o][c];
    g_And[b][o][c] = (c == o) ? 0.f : m;
    __shared__ float sh[256];
    __shared__ float mdiag;
    if (c == o) mdiag = m;
    sh[c] = g_att[b][o][c] * g_beta[b][2][c];
    __syncthreads();
    for (int off = 128; off > 0; off >>= 1) {
        if (c < off) sh[c] += sh[c + off];
        __syncthreads();
    }
    if (c == 0) {
        g_adiag[b][o] = mdiag + g_rstd[b][o];
        g_dvec[b][o]  = sh[0] - g_rstd[b][o] * g_mean[b][o];
    }
}

// ---------------- 8. final GEMM: out = A_nd @ x (single fp16 mma)
//                    + adiag*x (exact fp32) + dvec ----------------
#define BSTR 34   // Bs16 row stride in halves (even for 4B-aligned frag loads)
__global__ __launch_bounds__(256) void out_kernel(const float* __restrict__ x,
                                                  float* __restrict__ out) {
    int mt = blockIdx.x, nt = blockIdx.y, b = blockIdx.z;
    int m0 = mt * 128, n0 = nt * 128;
    const float* xb = x + (size_t)b * CC * NSP;
    float* ob = out + (size_t)b * CC * NSP;
    const float* Ab = &g_And[b][0][0];
    __shared__ __half Ah[128][KT + 8];
    __shared__ float  Bs[KT][132];       // fp32 x tile (k-major) for exact diag path
    __shared__ __half Bs16[128][BSTR];   // fp16 x tile (n-major) for mma fragments
    int tid = threadIdx.x, warp = tid >> 5, lane = tid & 31;
    int wm = warp & 1, wn = warp >> 1;
    float acc[4][4][4] = {};
    int   rows[4][2];
    float adv[4][2];
#pragma unroll
    for (int mi = 0; mi < 4; mi++)
#pragma unroll
        for (int rs = 0; rs < 2; rs++) {
            int r = wm * 64 + mi * 16 + (lane >> 2) + 8 * rs;
            rows[mi][rs] = r;
            adv[mi][rs] = g_adiag[b][m0 + r];
        }
    for (int kt = 0; kt < CC; kt += KT) {
#pragma unroll
        for (int i = 0; i < 4; i++) {        // A tile 128x32 -> fp16
            int idx = tid + i * 256;
            int r = idx >> 3, c4 = (idx & 7) << 2;
            float4 v = *(const float4*)(Ab + (size_t)(m0 + r) * CC + kt + c4);
            *(__half2*)&Ah[r][c4]     = __floats2half2_rn(v.x, v.y);
            *(__half2*)&Ah[r][c4 + 2] = __floats2half2_rn(v.z, v.w);
        }
#pragma unroll
        for (int i = 0; i < 4; i++) {        // x tile 32x128: fp32 k-major + fp16 n-major
            int idx = tid + i * 256;
            int kk = idx >> 5, c4 = (idx & 31) << 2;
            float4 v = *(const float4*)(xb + (size_t)(kt + kk) * NSP + n0 + c4);
            *(float4*)&Bs[kk][c4] = v;
            Bs16[c4 + 0][kk] = __float2half_rn(v.x);
            Bs16[c4 + 1][kk] = __float2half_rn(v.y);
            Bs16[c4 + 2][kk] = __float2half_rn(v.z);
            Bs16[c4 + 3][kk] = __float2half_rn(v.w);
        }
        __syncthreads();
#pragma unroll
        for (int ks = 0; ks < KT; ks += 16) {
            unsigned ah[4][4], bh[4][2];
#pragma unroll
            for (int mi = 0; mi < 4; mi++) {
                int rb = wm * 64 + mi * 16 + (lane >> 2);
                int cb = ks + ((lane & 3) << 1);
                ah[mi][0] = *(const unsigned*)&Ah[rb][cb];
                ah[mi][1] = *(const unsigned*)&Ah[rb + 8][cb];
                ah[mi][2] = *(const unsigned*)&Ah[rb][cb + 8];
                ah[mi][3] = *(const unsigned*)&Ah[rb + 8][cb + 8];
            }
#pragma unroll
            for (int ni = 0; ni < 4; ni++) {
                int nb = wn * 32 + ni * 8 + (lane >> 2);
                int kb = ks + ((lane & 3) << 1);
                bh[ni][0] = *(const unsigned*)&Bs16[nb][kb];
                bh[ni][1] = *(const unsigned*)&Bs16[nb][kb + 8];
            }
#pragma unroll
            for (int mi = 0; mi < 4; mi++)
#pragma unroll
                for (int ni = 0; ni < 4; ni++)
                    mma16(acc[mi][ni], ah[mi], bh[ni]);
        }
        // exact-fp32 diagonal (residual) contribution from this K tile
#pragma unroll
        for (int mi = 0; mi < 4; mi++)
#pragma unroll
            for (int rs = 0; rs < 2; rs++) {
                int gch = m0 + rows[mi][rs];
                if (gch >= kt && gch < kt + KT) {
                    int ks2 = gch - kt;
                    float av = adv[mi][rs];
#pragma unroll
                    for (int ni = 0; ni < 4; ni++) {
                        int nb = wn * 32 + ni * 8 + 2 * (lane & 3);
                        acc[mi][ni][rs * 2 + 0] += av * Bs[ks2][nb];
                        acc[mi][ni][rs * 2 + 1] += av * Bs[ks2][nb + 1];
                    }
                }
            }
        __syncthreads();
    }
#pragma unroll
    for (int mi = 0; mi < 4; mi++)
#pragma unroll
        for (int rs = 0; rs < 2; rs++) {
            int r = m0 + rows[mi][rs];
            float dv = g_dvec[b][r];
            float* orow = ob + (size_t)r * NSP + n0;
#pragma unroll
            for (int ni = 0; ni < 4; ni++) {
                int nb = wn * 32 + ni * 8 + 2 * (lane & 3);
                float2 v;
                v.x = acc[mi][ni][rs * 2 + 0] + dv;
                v.y = acc[mi][ni][rs * 2 + 1] + dv;
                *(float2*)&orow[nb] = v;
            }
        }
}

// ---------------- host ----------------
extern "C" void kernel_launch(void* const* d_in, const int* in_sizes, int n_in,
                              void* d_out, int out_size) {
    (void)in_sizes; (void)n_in; (void)out_size;
    const float* x     = (const float*)d_in[0];
    const float* Wq    = (const float*)d_in[1];
    const float* bq    = (const float*)d_in[2];
    const float* Wk    = (const float*)d_in[3];
    const float* bk    = (const float*)d_in[4];
    const float* Wv    = (const float*)d_in[5];
    const float* bv    = (const float*)d_in[6];
    const float* outer = (const float*)d_in[7];
    float* out = (float*)d_out;

    stats_kernel<<<dim3(CC, BATCH), 256>>>(x);
    mr_kernel<<<1, 512>>>();
    gram_kernel<<<dim3(3, NCHUNKS, BATCH), 256>>>(x);
    mirror_kernel<<<dim3(4, 4, BATCH), 256>>>();
    fold_kernel<<<dim3(CC, 3, BATCH), 256>>>(Wq, bq, Wk, bk, Wv, bv);
    sgemm_kernel<<<dim3(8, 8, BATCH), 256>>>(0);   // T1 = G @ Wk'^T
    sgemm_kernel<<<dim3(8, 8, BATCH), 256>>>(1);   // scores = Wq' @ T1 + rank1
    softmax_kernel<<<dim3(CC, BATCH), 256>>>(outer);
    sgemm_kernel<<<dim3(8, 8, BATCH), 256>>>(2);   // M = atten @ Wv'
    fin_kernel<<<dim3(CC, BATCH), 256>>>();
    out_kernel<<<dim3(2, 864, BATCH), 256>>>(x, out);
}

// round 8
// speedup vs baseline: 1.5112x; 1.3949x over previous
#include <cuda_runtime.h>
#include <cuda_fp16.h>

#define CC   256
#define NSP  110592   // 48^3 spatial
#define BATCH 2
#define EPS 1e-5f
#define GCHUNK 2048
#define NCHUNKS 54    // 54*2048 = 110592
#define KT 32

// ---------------- scratch (device globals; no allocation allowed) ----------------
__device__ float g_sum[BATCH][CC];
__device__ float g_mean[BATCH][CC];
__device__ float g_rstd[BATCH][CC];
__device__ float g_G[BATCH][CC][CC];
__device__ float g_Wp[BATCH][3][CC][CC];   // folded W' = W * diag(rstd), p=0:q 1:k 2:v
__device__ float g_beta[BATCH][3][CC];     // beta_p = b_p - W'_p @ mean
__device__ float g_u[BATCH][CC];           // Wq' @ rowsum(x)
__device__ float g_sv[BATCH][CC];          // Wk' @ rowsum(x)
__device__ float g_T1[BATCH][CC][CC];      // G @ Wk'^T
__device__ float g_scores[BATCH][CC][CC];
__device__ float g_att[BATCH][CC][CC];
__device__ float g_M[BATCH][CC][CC];       // atten @ Wv'
__device__ float g_And[BATCH][CC][CC];     // A with zeroed diagonal
__device__ float g_adiag[BATCH][CC];       // M[o,o] + rstd[o]
__device__ float g_dvec[BATCH][CC];        // atten@betav - rstd*mean

// ---------------- helpers ----------------
__device__ __forceinline__ void mma16(float* c, const unsigned* a, const unsigned* b) {
    asm volatile(
        "mma.sync.aligned.m16n8k16.row.col.f32.f16.f16.f32 "
        "{%0,%1,%2,%3}, {%4,%5,%6,%7}, {%8,%9}, {%0,%1,%2,%3};\n"
        : "+f"(c[0]), "+f"(c[1]), "+f"(c[2]), "+f"(c[3])
        : "r"(a[0]), "r"(a[1]), "r"(a[2]), "r"(a[3]), "r"(b[0]), "r"(b[1]));
}

// ---------------- 0. zero scratch (split 3-way so gram is launch #4 for ncu) ----------------
__global__ void zero_kernel(int part) {
    int tid = blockIdx.x * 256 + threadIdx.x;
    if (part < 2) {
        float4* p = (float4*)&g_G[part][0][0];     // 65536 floats = 16384 float4
        if (tid < 16384) p[tid] = make_float4(0.f, 0.f, 0.f, 0.f);
    } else {
        if (tid < BATCH * CC) ((float*)g_sum)[tid] = 0.f;
    }
}

// ---------------- 1. Gram: G = x @ x^T (fp16 mma, symmetric 3/4 tiles, prefetch,
//                    + row-sum accumulation in diag tiles) ----------------
__global__ __launch_bounds__(256) void gram_kernel(const float* __restrict__ x) {
    int tile = blockIdx.x, b = blockIdx.z;
    int diag = (tile < 2);
    int ti = (tile == 1) ? 1 : 0;
    int tj = (tile == 0) ? 0 : 1;
    size_t n0 = (size_t)blockIdx.y * GCHUNK;
    const float* xb = x + (size_t)b * CC * NSP;
    __shared__ __half As[128][KT + 8];
    __shared__ __half Bs[128][KT + 8];
    int tid = threadIdx.x, warp = tid >> 5, lane = tid & 31;
    int wm = warp & 1, wn = warp >> 1;   // 2 x 4 warp grid: 64x32 per warp
    float acc[4][4][4] = {};
    const float* Abase = xb + (size_t)(ti * 128) * NSP + n0;
    const float* Bbase = xb + (size_t)(tj * 128) * NSP + n0;
    int lr[4], lc[4];
#pragma unroll
    for (int i = 0; i < 4; i++) {
        int idx = tid + i * 256;
        lr[i] = idx >> 3;
        lc[i] = (idx & 7) << 2;
    }
    float rowsum[4] = {0.f, 0.f, 0.f, 0.f};
    float4 ra[4], rb[4];
    // prologue: load kt=0
#pragma unroll
    for (int i = 0; i < 4; i++) {
        ra[i] = *(const float4*)(Abase + (size_t)lr[i] * NSP + lc[i]);
        if (!diag) rb[i] = *(const float4*)(Bbase + (size_t)lr[i] * NSP + lc[i]);
    }
    for (int kt = 0; kt < GCHUNK; kt += KT) {
#pragma unroll
        for (int i = 0; i < 4; i++) {
            float4 v = ra[i];
            if (diag) rowsum[i] += v.x + v.y + v.z + v.w;
            *(__half2*)&As[lr[i]][lc[i]]     = __floats2half2_rn(v.x, v.y);
            *(__half2*)&As[lr[i]][lc[i] + 2] = __floats2half2_rn(v.z, v.w);
            if (!diag) {
                float4 w = rb[i];
                *(__half2*)&Bs[lr[i]][lc[i]]     = __floats2half2_rn(w.x, w.y);
                *(__half2*)&Bs[lr[i]][lc[i] + 2] = __floats2half2_rn(w.z, w.w);
            }
        }
        __syncthreads();
        if (kt + KT < GCHUNK) {     // prefetch next tile (overlaps mma below)
#pragma unroll
            for (int i = 0; i < 4; i++) {
                ra[i] = *(const float4*)(Abase + (size_t)lr[i] * NSP + kt + KT + lc[i]);
                if (!diag) rb[i] = *(const float4*)(Bbase + (size_t)lr[i] * NSP + kt + KT + lc[i]);
            }
        }
        __half (*Bp)[KT + 8] = diag ? As : Bs;
#pragma unroll
        for (int ks = 0; ks < KT; ks += 16) {
            unsigned af[4][4], bf[4][2];
#pragma unroll
            for (int mi = 0; mi < 4; mi++) {
                int rbr = wm * 64 + mi * 16 + (lane >> 2);
                int cb = ks + ((lane & 3) << 1);
                af[mi][0] = *(const unsigned*)&As[rbr][cb];
                af[mi][1] = *(const unsigned*)&As[rbr + 8][cb];
                af[mi][2] = *(const unsigned*)&As[rbr][cb + 8];
                af[mi][3] = *(const unsigned*)&As[rbr + 8][cb + 8];
            }
#pragma unroll
            for (int ni = 0; ni < 4; ni++) {
                int nb = wn * 32 + ni * 8 + (lane >> 2);
                int kb = ks + ((lane & 3) << 1);
                bf[ni][0] = *(const unsigned*)&Bp[nb][kb];
                bf[ni][1] = *(const unsigned*)&Bp[nb][kb + 8];
            }
#pragma unroll
            for (int mi = 0; mi < 4; mi++)
#pragma unroll
                for (int ni = 0; ni < 4; ni++)
                    mma16(acc[mi][ni], af[mi], bf[ni]);
        }
        __syncthreads();
    }
#pragma unroll
    for (int mi = 0; mi < 4; mi++)
#pragma unroll
        for (int ni = 0; ni < 4; ni++)
#pragma unroll
            for (int i = 0; i < 4; i++) {
                int row = ti * 128 + wm * 64 + mi * 16 + (lane >> 2) + 8 * (i >> 1);
                int col = tj * 128 + wn * 32 + ni * 8 + 2 * (lane & 3) + (i & 1);
                atomicAdd(&g_G[b][row][col], acc[mi][ni][i]);
            }
    if (diag) {
#pragma unroll
        for (int i = 0; i < 4; i++)
            atomicAdd(&g_sum[b][ti * 128 + lr[i]], rowsum[i]);
    }
}

// ---------------- 1b. mirror lower-left block: G[128+i][j] = G[j][128+i] ----------------
__global__ void mirror_kernel() {
    int b = blockIdx.z;
    int r0 = blockIdx.y * 32;          // source rows 0..127
    int c0 = 128 + blockIdx.x * 32;    // source cols 128..255
    __shared__ float sh[32][33];
    int tx = threadIdx.x & 31, ty = threadIdx.x >> 5;   // 32 x 8
#pragma unroll
    for (int i = 0; i < 4; i++)
        sh[ty + i * 8][tx] = g_G[b][r0 + ty + i * 8][c0 + tx];
    __syncthreads();
#pragma unroll
    for (int i = 0; i < 4; i++)
        g_G[b][c0 + ty + i * 8][r0 + tx] = sh[tx][ty + i * 8];
}

// ---------------- 2. mean / rstd (sum from gram, sumsq = diag(G)) ----------------
__global__ void mr_kernel() {
    int t = threadIdx.x;            // 512 threads
    int b = t >> 8, c = t & 255;
    float m = g_sum[b][c] * (1.f / (float)NSP);
    float var = g_G[b][c][c] * (1.f / (float)NSP) - m * m;
    g_mean[b][c] = m;
    g_rstd[b][c] = rsqrtf(var + EPS);
}

// ---------------- 3. fold weights + per-row dots ----------------
__global__ void fold_kernel(const float* __restrict__ Wq, const float* __restrict__ bq,
                            const float* __restrict__ Wk, const float* __restrict__ bk,
                            const float* __restrict__ Wv, const float* __restrict__ bv) {
    int o = blockIdx.x, p = blockIdx.y, b = blockIdx.z, c = threadIdx.x;
    const float* W    = (p == 0) ? Wq : (p == 1) ? Wk : Wv;
    const float* bias = (p == 0) ? bq : (p == 1) ? bk : bv;
    float wp = W[o * CC + c] * g_rstd[b][c];
    g_Wp[b][p][o][c] = wp;
    __shared__ float s1[256], s2[256];
    s1[c] = wp * g_mean[b][c];
    s2[c] = wp * g_sum[b][c];
    __syncthreads();
    for (int off = 128; off > 0; off >>= 1) {
        if (c < off) { s1[c] += s1[c + off]; s2[c] += s2[c + off]; }
        __syncthreads();
    }
    if (c == 0) {
        g_beta[b][p][o] = bias[o] - s1[0];
        if (p == 0) g_u[b][o]  = s2[0];
        if (p == 1) g_sv[b][o] = s2[0];
    }
}

// ---------------- 4. small 256x256x256 GEMMs (fp32, selector) ----------------
__global__ void sgemm_kernel(int which) {
    int b = blockIdx.z;
    const float *A, *B; float* Cm; int transB = 0, rank1 = 0;
    if (which == 0)      { A = &g_G[b][0][0];      B = &g_Wp[b][1][0][0]; Cm = &g_T1[b][0][0];     transB = 1; }
    else if (which == 1) { A = &g_Wp[b][0][0][0];  B = &g_T1[b][0][0];    Cm = &g_scores[b][0][0]; rank1 = 1;  }
    else                 { A = &g_att[b][0][0];    B = &g_Wp[b][2][0][0]; Cm = &g_M[b][0][0]; }
    int r0 = blockIdx.y * 32, c0 = blockIdx.x * 32;
    __shared__ float As[32][33], Bs[32][33];
    int tid = threadIdx.x;
    int tx = tid & 15, ty = tid >> 4;
    float acc[2][2] = {};
    for (int k0 = 0; k0 < CC; k0 += 32) {
#pragma unroll
        for (int t = 0; t < 4; t++) {
            int idx = tid + t * 256;
            int r = idx >> 5, cc = idx & 31;
            As[r][cc] = A[(r0 + r) * CC + k0 + cc];
            Bs[r][cc] = transB ? B[(c0 + cc) * CC + k0 + r] : B[(k0 + r) * CC + c0 + cc];
        }
        __syncthreads();
#pragma unroll
        for (int k = 0; k < 32; k++) {
            float a0 = As[ty * 2][k], a1 = As[ty * 2 + 1][k];
            float b0 = Bs[k][tx * 2], b1 = Bs[k][tx * 2 + 1];
            acc[0][0] += a0 * b0; acc[0][1] += a0 * b1;
            acc[1][0] += a1 * b0; acc[1][1] += a1 * b1;
        }
        __syncthreads();
    }
#pragma unroll
    for (int i = 0; i < 2; i++)
#pragma unroll
        for (int j = 0; j < 2; j++) {
            int r = r0 + ty * 2 + i, cc = c0 + tx * 2 + j;
            float v = acc[i][j];
            if (rank1)
                v += g_u[b][r] * g_beta[b][1][cc]
                   + g_beta[b][0][r] * g_sv[b][cc]
                   + (float)NSP * g_beta[b][0][r] * g_beta[b][1][cc];
            Cm[r * CC + cc] = v;
        }
}

// ---------------- 5. softmax rows -> atten ----------------
__global__ void softmax_kernel(const float* __restrict__ outer) {
    int o = blockIdx.x, b = blockIdx.y, d = threadIdx.x;
    float v = g_scores[b][o][d];
    __shared__ float sh[256];
    sh[d] = v; __syncthreads();
    for (int off = 128; off > 0; off >>= 1) {
        if (d < off) sh[d] = fmaxf(sh[d], sh[d + off]);
        __syncthreads();
    }
    float mx = sh[0]; __syncthreads();
    float e = expf(v - mx);
    sh[d] = e; __syncthreads();
    for (int off = 128; off > 0; off >>= 1) {
        if (d < off) sh[d] += sh[d + off];
        __syncthreads();
    }
    float inv = 1.f / sh[0];
    g_att[b][o][d] = e * inv * 0.0625f + outer[o * CC + d] * 0.0625f;
}

// ---------------- 6. finalize A_nd / adiag / dvec ----------------
__global__ void fin_kernel() {
    int o = blockIdx.x, b = blockIdx.y, c = threadIdx.x;
    float m = g_M[b][o][c];
    g_And[b][o][c] = (c == o) ? 0.f : m;
    __shared__ float sh[256];
    __shared__ float mdiag;
    if (c == o) mdiag = m;
    sh[c] = g_att[b][o][c] * g_beta[b][2][c];
    __syncthreads();
    for (int off = 128; off > 0; off >>= 1) {
        if (c < off) sh[c] += sh[c + off];
        __syncthreads();
    }
    if (c == 0) {
        g_adiag[b][o] = mdiag + g_rstd[b][o];
        g_dvec[b][o]  = sh[0] - g_rstd[b][o] * g_mean[b][o];
    }
}

// ---------------- 7. final GEMM: out = A_nd @ x (fp16 mma, prefetch)
//                    + adiag*x (exact fp32) + dvec ----------------
#define BSTR 34   // Bs16 row stride in halves
__global__ __launch_bounds__(256) void out_kernel(const float* __restrict__ x,
                                                  float* __restrict__ out) {
    int mt = blockIdx.x, nt = blockIdx.y, b = blockIdx.z;
    int m0 = mt * 128, n0 = nt * 128;
    const float* xb = x + (size_t)b * CC * NSP;
    float* ob = out + (size_t)b * CC * NSP;
    const float* Ab = &g_And[b][0][0];
    __shared__ __half Ah[128][KT + 8];
    __shared__ float  Bs[KT][132];       // fp32 x tile (k-major) for exact diag path
    __shared__ __half Bs16[128][BSTR];   // fp16 x tile (n-major) for mma fragments
    int tid = threadIdx.x, warp = tid >> 5, lane = tid & 31;
    int wm = warp & 1, wn = warp >> 1;
    float acc[4][4][4] = {};
    int   rows[4][2];
    float adv[4][2];
#pragma unroll
    for (int mi = 0; mi < 4; mi++)
#pragma unroll
        for (int rs = 0; rs < 2; rs++) {
            int r = wm * 64 + mi * 16 + (lane >> 2) + 8 * rs;
            rows[mi][rs] = r;
            adv[mi][rs] = g_adiag[b][m0 + r];
        }
    int ar[4], ac[4], xk[4], xc[4];
#pragma unroll
    for (int i = 0; i < 4; i++) {
        int idx = tid + i * 256;
        ar[i] = idx >> 3; ac[i] = (idx & 7) << 2;      // A tile coords
        xk[i] = idx >> 5; xc[i] = (idx & 31) << 2;     // x tile coords
    }
    float4 ra[4], rb[4];
#pragma unroll
    for (int i = 0; i < 4; i++) {       // prologue kt=0
        ra[i] = *(const float4*)(Ab + (size_t)(m0 + ar[i]) * CC + ac[i]);
        rb[i] = *(const float4*)(xb + (size_t)xk[i] * NSP + n0 + xc[i]);
    }
    for (int kt = 0; kt < CC; kt += KT) {
#pragma unroll
        for (int i = 0; i < 4; i++) {        // A tile -> fp16 smem
            float4 v = ra[i];
            *(__half2*)&Ah[ar[i]][ac[i]]     = __floats2half2_rn(v.x, v.y);
            *(__half2*)&Ah[ar[i]][ac[i] + 2] = __floats2half2_rn(v.z, v.w);
            float4 w = rb[i];
            *(float4*)&Bs[xk[i]][xc[i]] = w;
            Bs16[xc[i] + 0][xk[i]] = __float2half_rn(w.x);
            Bs16[xc[i] + 1][xk[i]] = __float2half_rn(w.y);
            Bs16[xc[i] + 2][xk[i]] = __float2half_rn(w.z);
            Bs16[xc[i] + 3][xk[i]] = __float2half_rn(w.w);
        }
        __syncthreads();
        if (kt + KT < CC) {              // prefetch next (overlaps mma)
#pragma unroll
            for (int i = 0; i < 4; i++) {
                ra[i] = *(const float4*)(Ab + (size_t)(m0 + ar[i]) * CC + kt + KT + ac[i]);
                rb[i] = *(const float4*)(xb + (size_t)(kt + KT + xk[i]) * NSP + n0 + xc[i]);
            }
        }
#pragma unroll
        for (int ks = 0; ks < KT; ks += 16) {
            unsigned ah[4][4], bh[4][2];
#pragma unroll
            for (int mi = 0; mi < 4; mi++) {
                int rbr = wm * 64 + mi * 16 + (lane >> 2);
                int cb = ks + ((lane & 3) << 1);
                ah[mi][0] = *(const unsigned*)&Ah[rbr][cb];
                ah[mi][1] = *(const unsigned*)&Ah[rbr + 8][cb];
                ah[mi][2] = *(const unsigned*)&Ah[rbr][cb + 8];
                ah[mi][3] = *(const unsigned*)&Ah[rbr + 8][cb + 8];
            }
#pragma unroll
            for (int ni = 0; ni < 4; ni++) {
                int nb = wn * 32 + ni * 8 + (lane >> 2);
                int kb = ks + ((lane & 3) << 1);
                bh[ni][0] = *(const unsigned*)&Bs16[nb][kb];
                bh[ni][1] = *(const unsigned*)&Bs16[nb][kb + 8];
            }
#pragma unroll
            for (int mi = 0; mi < 4; mi++)
#pragma unroll
                for (int ni = 0; ni < 4; ni++)
                    mma16(acc[mi][ni], ah[mi], bh[ni]);
        }
        // exact-fp32 diagonal (residual) contribution from this K tile
#pragma unroll
        for (int mi = 0; mi < 4; mi++)
#pragma unroll
            for (int rs = 0; rs < 2; rs++) {
                int gch = m0 + rows[mi][rs];
                if (gch >= kt && gch < kt + KT) {
                    int ks2 = gch - kt;
                    float av = adv[mi][rs];
#pragma unroll
                    for (int ni = 0; ni < 4; ni++) {
                        int nb = wn * 32 + ni * 8 + 2 * (lane & 3);
                        acc[mi][ni][rs * 2 + 0] += av * Bs[ks2][nb];
                        acc[mi][ni][rs * 2 + 1] += av * Bs[ks2][nb + 1];
                    }
                }
            }
        __syncthreads();
    }
#pragma unroll
    for (int mi = 0; mi < 4; mi++)
#pragma unroll
        for (int rs = 0; rs < 2; rs++) {
            int r = m0 + rows[mi][rs];
            float dv = g_dvec[b][r];
            float* orow = ob + (size_t)r * NSP + n0;
#pragma unroll
            for (int ni = 0; ni < 4; ni++) {
                int nb = wn * 32 + ni * 8 + 2 * (lane & 3);
                float2 v;
                v.x = acc[mi][ni][rs * 2 + 0] + dv;
                v.y = acc[mi][ni][rs * 2 + 1] + dv;
                *(float2*)&orow[nb] = v;
            }
        }
}

// ---------------- host ----------------
extern "C" void kernel_launch(void* const* d_in, const int* in_sizes, int n_in,
                              void* d_out, int out_size) {
    (void)in_sizes; (void)n_in; (void)out_size;
    const float* x     = (const float*)d_in[0];
    const float* Wq    = (const float*)d_in[1];
    const float* bq    = (const float*)d_in[2];
    const float* Wk    = (const float*)d_in[3];
    const float* bk    = (const float*)d_in[4];
    const float* Wv    = (const float*)d_in[5];
    const float* bv    = (const float*)d_in[6];
    const float* outer = (const float*)d_in[7];
    float* out = (float*)d_out;

    zero_kernel<<<64, 256>>>(0);                        // #1
    zero_kernel<<<64, 256>>>(1);                        // #2
    zero_kernel<<<2, 256>>>(2);                         // #3
    gram_kernel<<<dim3(3, NCHUNKS, BATCH), 256>>>(x);   // #4  <- ncu capture slot
    mirror_kernel<<<dim3(4, 4, BATCH), 256>>>();
    mr_kernel<<<1, 512>>>();
    fold_kernel<<<dim3(CC, 3, BATCH), 256>>>(Wq, bq, Wk, bk, Wv, bv);
    sgemm_kernel<<<dim3(8, 8, BATCH), 256>>>(0);   // T1 = G @ Wk'^T
    sgemm_kernel<<<dim3(8, 8, BATCH), 256>>>(1);   // scores = Wq' @ T1 + rank1
    softmax_kernel<<<dim3(CC, BATCH), 256>>>(outer);
    sgemm_kernel<<<dim3(8, 8, BATCH), 256>>>(2);   // M = atten @ Wv'
    fin_kernel<<<dim3(CC, BATCH), 256>>>();
    out_kernel<<<dim3(2, 864, BATCH), 256>>>(x, out);
}